// round 16
// baseline (speedup 1.0000x reference)
#include <cuda_runtime.h>
#include <cuda_bf16.h>
#include <stdint.h>
#include <math.h>

// ---------------------------------------------------------------- constants
#define BATCH   2
#define NQ      16384
#define NATOMS  1024
#define KDIM    256
#define ODIM    256
#define NROWS   (BATCH * NQ)
#define OMEGA0  30.0f
#define EPSD    1e-4f

#define BM      128
#define BN      128
#define BKC     32
#define NCHUNK  (KDIM / BKC)     // 8
#define NTHREADS 512

#define SPLIT_CTAS 256           // one per 128-row block: omega + X bf16 split
#define GEMM_CTAS  ((NROWS / BM) * (ODIM / BN))   // 512

// SMEM: A ring 2 x 16KB @0, B ring 2 x 16KB @32768 (stage: s*8192 + [hi 4K|lo 4K],
// rows 32B, XOR bit7->bit4 swizzle). Epilogue staging needs 67584.
#define OFF_A   0
#define OFF_B   32768
#define SM_BYTES 67584
#define EPI_STRIDE 132
#define PAD4    4112             // splitter atom partition stride (256 float4 + 16B)

static __device__ __nv_bfloat16 g_Whi[ODIM * KDIM];
static __device__ __nv_bfloat16 g_Wlo[ODIM * KDIM];
static __device__ __nv_bfloat16 g_Xhi[NROWS * KDIM];
static __device__ __nv_bfloat16 g_Xlo[NROWS * KDIM];
static __device__ float         g_omega[NROWS];
static __device__ int           g_flags[SPLIT_CTAS];

// ---------------------------------------------------------------- helpers
__device__ __forceinline__ uint32_t smem_u32(const void* p) {
    uint32_t a;
    asm("{ .reg .u64 t; cvta.to.shared.u64 t, %1; cvt.u32.u64 %0, t; }" : "=r"(a) : "l"(p));
    return a;
}
__device__ __forceinline__ uint32_t swz32(uint32_t o) { return o ^ ((o >> 3) & 0x10); }

__device__ __forceinline__ void cp16(uint32_t dst, const void* src) {
    asm volatile("cp.async.cg.shared.global [%0], [%1], 16;" :: "r"(dst), "l"(src));
}
#define CP_COMMIT() asm volatile("cp.async.commit_group;")
#define CP_WAIT0()  asm volatile("cp.async.wait_group 0;")

#define LDSM4(r, a) \
    asm volatile("ldmatrix.sync.aligned.m8n8.x4.shared.b16 {%0,%1,%2,%3}, [%4];" \
        : "=r"((r)[0]), "=r"((r)[1]), "=r"((r)[2]), "=r"((r)[3]) : "r"(a))

__device__ __forceinline__ void mma_bf16(float* c, const uint32_t* a,
                                         uint32_t b0, uint32_t b1) {
    asm volatile(
        "mma.sync.aligned.m16n8k16.row.col.f32.bf16.bf16.f32 "
        "{%0,%1,%2,%3}, {%4,%5,%6,%7}, {%8,%9}, {%0,%1,%2,%3};"
        : "+f"(c[0]), "+f"(c[1]), "+f"(c[2]), "+f"(c[3])
        : "r"(a[0]), "r"(a[1]), "r"(a[2]), "r"(a[3]), "r"(b0), "r"(b1));
}
__device__ __forceinline__ uint32_t packsplit(float x, float y, uint32_t& lo) {
    uint32_t h;
    asm("cvt.rn.bf16x2.f32 %0, %1, %2;" : "=r"(h) : "f"(y), "f"(x));
    float hx = __uint_as_float(h << 16);
    float hy = __uint_as_float(h & 0xffff0000u);
    float rx = x - hx, ry = y - hy;
    asm("cvt.rn.bf16x2.f32 %0, %1, %2;" : "=r"(lo) : "f"(ry), "f"(rx));
    return h;
}

// ---------------------------------------------------------------- prep: W split + flag reset
__global__ __launch_bounds__(256)
void prep_w(const float* __restrict__ W)
{
    if (threadIdx.x == 0) g_flags[blockIdx.x] = 0;
    int i = blockIdx.x * 256 + threadIdx.x;
    float w = W[i];
    __nv_bfloat16 h = __float2bfloat16(w);
    g_Whi[i] = h;
    g_Wlo[i] = __float2bfloat16(w - __bfloat162float(h));
}

// ---------------------------------------------------------------- main kernel
__global__ __launch_bounds__(NTHREADS, 2)
void siren_main(const float* __restrict__ X, const float* __restrict__ Q,
                const float* __restrict__ atoms, const float* __restrict__ bias,
                const float* __restrict__ fw1, const float* __restrict__ fb1,
                const float* __restrict__ fw2, const float* __restrict__ fb2,
                float* __restrict__ out)
{
    extern __shared__ char sb[];
    const uint32_t sbase = smem_u32(sb);
    const int tid = threadIdx.x;

    // ============ splitter CTAs (wave 1): omega + X split for 128 rows ============
    if (blockIdx.x < SPLIT_CTAS) {
        const int blk = blockIdx.x;
        const int q0 = blk * 128;
        const int batch = (q0 >= NQ) ? 1 : 0;
        const float* ab = atoms + (size_t)batch * NATOMS * 3;
        // atoms into 4 padded partitions (bank-conflict-free scan)
        for (int j = tid; j < NATOMS; j += NTHREADS) {
            float ax = ab[3*j], ay = ab[3*j+1], az = ab[3*j+2];
            *(float4*)(sb + (j >> 8) * PAD4 + (j & 255) * 16) =
                make_float4(ax, ay, az, fmaf(ax, ax, fmaf(ay, ay, az*az)));
        }
        __syncthreads();

        // omega: 4 threads per query
        {
            const int qi = q0 + (tid >> 2);
            const int part = tid & 3;
            const float* qp = Q + (size_t)qi * 3;
            float qx = qp[0], qy = qp[1], qz = qp[2];
            float nqx = -2.f * qx, nqy = -2.f * qy, nqz = -2.f * qz;
            const float4* at = (const float4*)(sb + part * PAD4);
            float m0 = 3.4e38f, m1 = 3.4e38f;
#pragma unroll 4
            for (int j = 0; j < 256; j += 2) {
                float4 a0 = at[j], a1 = at[j + 1];
                m0 = fminf(m0, fmaf(a0.x, nqx, fmaf(a0.y, nqy, fmaf(a0.z, nqz, a0.w))));
                m1 = fminf(m1, fmaf(a1.x, nqx, fmaf(a1.y, nqy, fmaf(a1.z, nqz, a1.w))));
            }
            float md = fminf(m0, m1);
            md = fminf(md, __shfl_xor_sync(0xffffffffu, md, 1));
            md = fminf(md, __shfl_xor_sync(0xffffffffu, md, 2));
            if (part == 0) {
                float qsq = fmaf(qx, qx, fmaf(qy, qy, qz * qz));
                float mind = sqrtf(fmaxf(md + qsq, EPSD));
                float ls = __ldg(fb2);
#pragma unroll
                for (int j = 0; j < 16; ++j) {
                    float z = fmaf(__ldg(fw1 + 3*j), qx,
                              fmaf(__ldg(fw1 + 3*j + 1), qy,
                              fmaf(__ldg(fw1 + 3*j + 2), qz, __ldg(fb1 + j))));
                    float sp = fmaxf(z, 0.0f) + log1pf(expf(-fabsf(z)));
                    ls = fmaf(__ldg(fw2 + j), sp, ls);
                }
                ls = fminf(fmaxf(ls, 0.0f), 5.0f);
                g_omega[qi] = OMEGA0 * (1.0f + ls * expf(-mind));
            }
        }

        // X bf16 hi/lo split: 128 rows = 8192 float4 units
        {
            const float4* Xs = (const float4*)(X + (size_t)q0 * KDIM);
            uint2* Hp = (uint2*)(g_Xhi + (size_t)q0 * KDIM);
            uint2* Lp = (uint2*)(g_Xlo + (size_t)q0 * KDIM);
#pragma unroll 4
            for (int i = 0; i < 16; ++i) {
                int u = tid + i * NTHREADS;
                float4 v = Xs[u];
                uint2 hi, lo;
                hi.x = packsplit(v.x, v.y, lo.x);
                hi.y = packsplit(v.z, v.w, lo.y);
                Hp[u] = hi;
                Lp[u] = lo;
            }
        }
        __threadfence();
        __syncthreads();
        if (tid == 0) atomicExch(&g_flags[blk], 1);
        return;
    }

    // ============ GEMM CTAs: 128x128, 16 warps (4M x 4N), pure async mainloop ====
    const int bid  = blockIdx.x - SPLIT_CTAS;
    const int lane = tid & 31;
    const int wid  = tid >> 5;
    const int blk  = bid >> 1;
    const int gRow0 = blk * BM;
    const int gCol0 = (bid & 1) * BN;

    const int warpM = (wid & 3) * 32;
    const int warpN = (wid >> 2) * 32;
    const int lr = lane >> 2;
    const int lc = (lane & 3) * 2;
    const int l7 = lane & 7, g = lane >> 3;
    const uint32_t aoff = swz32((uint32_t)((warpM + l7 + (g & 1) * 8) * 32 + ((g >> 1) & 1) * 16));
    const uint32_t boff = swz32((uint32_t)((warpN + l7 + ((g >> 1) & 1) * 8) * 32 + (g & 1) * 16));

    auto prefB = [&](int c) {   // 2 cp16/thread
#pragma unroll
        for (int i = 0; i < 2; ++i) {
            int u = tid + i * NTHREADS;          // 0..1023
            int mat = u >> 9, m = u & 511;
            int n = m >> 2, t = m & 3, s = t >> 1, e = t & 1;
            uint32_t d = sbase + OFF_B + (uint32_t)(c & 1) * 16384 + s * 8192 + mat * 4096
                       + (swz32((uint32_t)(n * 32)) ^ (uint32_t)(e * 16));
            const __nv_bfloat16* src = mat ? g_Wlo : g_Whi;
            cp16(d, src + (gCol0 + n) * KDIM + c * BKC + s * 16 + e * 8);
        }
    };
    auto prefA = [&](int c) {   // 2 cp16/thread
#pragma unroll
        for (int i = 0; i < 2; ++i) {
            int u = tid + i * NTHREADS;
            int mat = u >> 9, m = u & 511;
            int r = m >> 2, t = m & 3, s = t >> 1, e = t & 1;
            uint32_t d = sbase + OFF_A + (uint32_t)(c & 1) * 16384 + s * 8192 + mat * 4096
                       + (swz32((uint32_t)(r * 32)) ^ (uint32_t)(e * 16));
            const __nv_bfloat16* src = mat ? g_Xlo : g_Xhi;
            cp16(d, src + (size_t)(gRow0 + r) * KDIM + c * BKC + s * 16 + e * 8);
        }
    };

    // ---- prologue: B(0) prefetch, then wait for this block's splitter, then A(0)
    prefB(0);
    CP_COMMIT();
    if (tid == 0) {
        int v;
        do {
            asm volatile("ld.acquire.gpu.global.b32 %0, [%1];" : "=r"(v) : "l"(&g_flags[blk]));
        } while (!v);
    }
    __syncthreads();
    prefA(0);
    CP_COMMIT();

    float acc[2][4][4];
#pragma unroll
    for (int i = 0; i < 2; ++i)
#pragma unroll
        for (int j = 0; j < 4; ++j)
#pragma unroll
            for (int k = 0; k < 4; ++k) acc[i][j][k] = 0.0f;

    // ---- main loop: wait -> barrier -> prefetch(c+1) -> compute(c) ----
#pragma unroll 1
    for (int c = 0; c < NCHUNK; ++c) {
        CP_WAIT0();
        __syncthreads();
        if (c + 1 < NCHUNK) { prefA(c + 1); prefB(c + 1); CP_COMMIT(); }

        const uint32_t Ast = sbase + OFF_A + (uint32_t)(c & 1) * 16384;
        const uint32_t Bst = sbase + OFF_B + (uint32_t)(c & 1) * 16384;
#pragma unroll
        for (int s = 0; s < 2; ++s) {
            const uint32_t ab = Ast + s * 8192 + aoff;
            const uint32_t bb = Bst + s * 8192 + boff;
            uint32_t ah[2][4], al[2][4], bq[2][4];
            LDSM4(ah[0], ab);
            LDSM4(ah[1], ab + 512);
            LDSM4(al[0], ab + 4096);
            LDSM4(al[1], ab + 4096 + 512);
            LDSM4(bq[0], bb);
            LDSM4(bq[1], bb + 512);
            // pass 1: hi*HI
#pragma unroll
            for (int mt = 0; mt < 2; ++mt)
#pragma unroll
                for (int p = 0; p < 2; ++p) {
                    mma_bf16(acc[mt][2*p],   ah[mt], bq[p][0], bq[p][1]);
                    mma_bf16(acc[mt][2*p+1], ah[mt], bq[p][2], bq[p][3]);
                }
            // pass 2: lo*HI
#pragma unroll
            for (int mt = 0; mt < 2; ++mt)
#pragma unroll
                for (int p = 0; p < 2; ++p) {
                    mma_bf16(acc[mt][2*p],   al[mt], bq[p][0], bq[p][1]);
                    mma_bf16(acc[mt][2*p+1], al[mt], bq[p][2], bq[p][3]);
                }
            // pass 3: hi*LO
            LDSM4(bq[0], bb + 4096);
            LDSM4(bq[1], bb + 4096 + 512);
#pragma unroll
            for (int mt = 0; mt < 2; ++mt)
#pragma unroll
                for (int p = 0; p < 2; ++p) {
                    mma_bf16(acc[mt][2*p],   ah[mt], bq[p][0], bq[p][1]);
                    mma_bf16(acc[mt][2*p+1], ah[mt], bq[p][2], bq[p][3]);
                }
        }
    }
    __syncthreads();            // all tile reads done; smem free

    // ---- epilogue: sin(omega*(acc+bias)) -> SMEM -> coalesced STG ----
    float* stg = (float*)sb;
#pragma unroll
    for (int mt = 0; mt < 2; ++mt) {
        int r0 = warpM + mt * 16 + lr;
        float o0 = __ldg(g_omega + gRow0 + r0);
        float o1 = __ldg(g_omega + gRow0 + r0 + 8);
#pragma unroll
        for (int nt = 0; nt < 4; ++nt) {
            int c0 = warpN + nt * 8 + lc;
            float b0 = __ldg(bias + gCol0 + c0), b1 = __ldg(bias + gCol0 + c0 + 1);
            float* a = acc[mt][nt];
            *(float2*)(stg + r0 * EPI_STRIDE + c0) =
                make_float2(__sinf(o0 * (a[0] + b0)), __sinf(o0 * (a[1] + b1)));
            *(float2*)(stg + (r0 + 8) * EPI_STRIDE + c0) =
                make_float2(__sinf(o1 * (a[2] + b0)), __sinf(o1 * (a[3] + b1)));
        }
    }
    __syncthreads();
#pragma unroll
    for (int i = 0; i < 8; ++i) {
        int lin = tid + i * NTHREADS;
        int rr = lin >> 5, c4 = (lin & 31) * 4;
        *(float4*)(out + (size_t)(gRow0 + rr) * ODIM + gCol0 + c4) =
            *(const float4*)(stg + rr * EPI_STRIDE + c4);
    }
}

// ---------------------------------------------------------------- launch
extern "C" void kernel_launch(void* const* d_in, const int* in_sizes, int n_in,
                              void* d_out, int out_size)
{
    const float* x     = (const float*)d_in[0];
    const float* q     = (const float*)d_in[1];
    const float* atoms = (const float*)d_in[2];
    const float* W     = (const float*)d_in[3];
    const float* bias  = (const float*)d_in[4];
    const float* fw1   = (const float*)d_in[5];
    const float* fb1   = (const float*)d_in[6];
    const float* fw2   = (const float*)d_in[7];
    const float* fb2   = (const float*)d_in[8];
    float* out = (float*)d_out;
    (void)in_sizes; (void)n_in; (void)out_size;

    cudaFuncSetAttribute(siren_main, cudaFuncAttributeMaxDynamicSharedMemorySize, SM_BYTES);

    prep_w<<<SPLIT_CTAS, 256>>>(W);
    siren_main<<<SPLIT_CTAS + GEMM_CTAS, NTHREADS, SM_BYTES>>>(
        x, q, atoms, bias, fw1, fb1, fw2, fb2, out);
}